// round 5
// baseline (speedup 1.0000x reference)
#include <cuda_runtime.h>
#include <stdint.h>

// RoPE: x (B,H,S,128) fp32, token_positions (S,) int32,
// cos_table/sin_table (8192, 64) fp32.
//
// CTA owns 1024 contiguous float4s = 32 head-rows = 32 positions.
// cos/sin rows for those positions are staged in shared memory once per CTA
// (coalesced float4 loads), so the steady-state global traffic is exactly
// one LDG.128 + one STG.128 per output float4.

#define THREADS 256
#define UN 4
#define CHUNK (THREADS * UN)          // 1024 float4
#define ROWS_PER_CTA 32               // CHUNK / 32

template<bool POW2>
__global__ void __launch_bounds__(THREADS)
rope_smem(const float4* __restrict__ x,
          const int*    __restrict__ tok_pos,
          const float4* __restrict__ cos_t,   // row = 16 float4
          const float4* __restrict__ sin_t,
          float4*       __restrict__ out,
          int seq, int seq_mask)
{
    __shared__ float s_cos[ROWS_PER_CTA * 64];
    __shared__ float s_sin[ROWS_PER_CTA * 64];
    __shared__ int   s_pos[ROWS_PER_CTA];

    const int t    = threadIdx.x;
    const int base = blockIdx.x * CHUNK + t;

    // Front-issue the 4 independent DRAM loads so they overlap table staging.
    float4 v[UN];
#pragma unroll
    for (int k = 0; k < UN; k++)
        v[k] = x[base + k * THREADS];

    // Stage token positions for this CTA's 32 rows.
    if (t < ROWS_PER_CTA) {
        int row = blockIdx.x * ROWS_PER_CTA + t;
        int pos = POW2 ? (row & seq_mask) : (row % seq);
        s_pos[t] = __ldg(&tok_pos[pos]);
    }
    __syncthreads();

    // Stage cos/sin rows: 32 rows x 16 float4 per table = 512 float4 each.
    float4* s_cos4 = reinterpret_cast<float4*>(s_cos);
    float4* s_sin4 = reinterpret_cast<float4*>(s_sin);
#pragma unroll
    for (int j = 0; j < 2; j++) {
        int idx = t + j * THREADS;        // 0..511
        int r   = idx >> 4;               // table-row slot
        int col = idx & 15;
        int p   = s_pos[r];
        s_cos4[idx] = __ldg(&cos_t[p * 16 + col]);
        s_sin4[idx] = __ldg(&sin_t[p * 16 + col]);
    }
    __syncthreads();

    // Compute: table reads from smem (float2, conflict-free), then store.
    const int q   = t & 31;               // float4 col within 128-elem row
    const int rl0 = t >> 5;               // local row for k=0
#pragma unroll
    for (int k = 0; k < UN; k++) {
        int rl = rl0 + k * (THREADS / 32);
        float2 c = *reinterpret_cast<const float2*>(&s_cos[rl * 64 + 2 * q]);
        float2 s = *reinterpret_cast<const float2*>(&s_sin[rl * 64 + 2 * q]);
        float4 o;
        o.x = fmaf(c.x, v[k].x, -s.x * v[k].y);
        o.y = fmaf(s.x, v[k].x,  c.x * v[k].y);
        o.z = fmaf(c.y, v[k].z, -s.y * v[k].w);
        o.w = fmaf(s.y, v[k].z,  c.y * v[k].w);
        out[base + k * THREADS] = o;
    }
}

// Checked tail for n4 not divisible by CHUNK (direct L2 gathers).
template<bool POW2>
__global__ void __launch_bounds__(THREADS)
rope_tail(const float4* __restrict__ x,
          const int*    __restrict__ tok_pos,
          const float2* __restrict__ cos_t,
          const float2* __restrict__ sin_t,
          float4*       __restrict__ out,
          int start, int n4, int seq, int seq_mask)
{
    int i = start + blockIdx.x * blockDim.x + threadIdx.x;
    if (i >= n4) return;
    int row = i >> 5;
    int q   = i & 31;
    int pos = POW2 ? (row & seq_mask) : (row % seq);
    int p   = __ldg(&tok_pos[pos]);
    float2 c = __ldg(&cos_t[p * 32 + q]);
    float2 s = __ldg(&sin_t[p * 32 + q]);
    float4 v = x[i];
    float4 o;
    o.x = fmaf(c.x, v.x, -s.x * v.y);
    o.y = fmaf(s.x, v.x,  c.x * v.y);
    o.z = fmaf(c.y, v.z, -s.y * v.w);
    o.w = fmaf(s.y, v.z,  c.y * v.w);
    out[i] = o;
}

extern "C" void kernel_launch(void* const* d_in, const int* in_sizes, int n_in,
                              void* d_out, int out_size)
{
    const float4* x     = (const float4*)d_in[0];
    const int*    tpos  = (const int*)   d_in[1];
    const float4* cos_t = (const float4*)d_in[2];
    const float4* sin_t = (const float4*)d_in[3];
    float4*       out   = (float4*)      d_out;

    int seq = in_sizes[1];
    int n4  = out_size / 4;

    int  blocks = n4 / CHUNK;
    int  n_bulk = blocks * CHUNK;
    int  tail   = n4 - n_bulk;
    bool pow2   = (seq & (seq - 1)) == 0;

    if (blocks > 0) {
        if (pow2)
            rope_smem<true ><<<blocks, THREADS>>>(x, tpos, cos_t, sin_t, out,
                                                  seq, seq - 1);
        else
            rope_smem<false><<<blocks, THREADS>>>(x, tpos, cos_t, sin_t, out,
                                                  seq, 0);
    }
    if (tail > 0) {
        int tblocks = (tail + THREADS - 1) / THREADS;
        if (pow2)
            rope_tail<true ><<<tblocks, THREADS>>>(x, tpos,
                                                   (const float2*)cos_t,
                                                   (const float2*)sin_t, out,
                                                   n_bulk, n4, seq, seq - 1);
        else
            rope_tail<false><<<tblocks, THREADS>>>(x, tpos,
                                                   (const float2*)cos_t,
                                                   (const float2*)sin_t, out,
                                                   n_bulk, n4, seq, 0);
    }
}